// round 12
// baseline (speedup 1.0000x reference)
#include <cuda_runtime.h>
#include <cstdint>

#define C 128
#define G 100000
#define NPTS_MAX 1000000

// Scratch (device globals — no allocation).
__device__ int g_hist[G];        // per-group counts
__device__ int g_base[1];        // global offset counter
__device__ int g_ofs[G];         // per-group start offset into perm
__device__ int g_cur[G];         // running cursor (consumed by perm_kernel)
__device__ int g_perm[NPTS_MAX]; // point indices, grouped contiguously

// ---------------------------------------------------------------------------
// 0) zero histogram + global counter (proven graph-capturable)
// ---------------------------------------------------------------------------
__global__ void init_kernel() {
    int idx = blockIdx.x * blockDim.x + threadIdx.x;
    int stride = gridDim.x * blockDim.x;
    for (int i = idx; i < G; i += stride) g_hist[i] = 0;
    if (idx == 0) g_base[0] = 0;
}

// ---------------------------------------------------------------------------
// 1) histogram of group ids — int4 vectorized, 4 atomics/thread (MLP=4)
// ---------------------------------------------------------------------------
__global__ void __launch_bounds__(256) hist_kernel(
    const int* __restrict__ gid, int n4, int n)
{
    int i = blockIdx.x * blockDim.x + threadIdx.x;
    if (i < n4) {
        int4 g4 = reinterpret_cast<const int4*>(gid)[i];
        atomicAdd(&g_hist[min(max(g4.x, 0), G - 1)], 1);
        atomicAdd(&g_hist[min(max(g4.y, 0), G - 1)], 1);
        atomicAdd(&g_hist[min(max(g4.z, 0), G - 1)], 1);
        atomicAdd(&g_hist[min(max(g4.w, 0), G - 1)], 1);
    }
    // tail (n not divisible by 4)
    int t = n4 * 4 + i;
    if (i < (n - n4 * 4)) {
        int g = gid[t];
        atomicAdd(&g_hist[min(max(g, 0), G - 1)], 1);
    }
}

// ---------------------------------------------------------------------------
// 2) offsets: block-local exclusive scan + one atomicAdd per block for the
//    global base. Group ordering across blocks is nondeterministic; fine.
// ---------------------------------------------------------------------------
__global__ void __launch_bounds__(256) offsets_kernel()
{
    __shared__ int s[256];
    __shared__ int base;
    int t = threadIdx.x;
    int g = blockIdx.x * 256 + t;
    int cnt = (g < G) ? g_hist[g] : 0;
    s[t] = cnt;
    __syncthreads();
    for (int d = 1; d < 256; d <<= 1) {
        int v = 0;
        if (t >= d) v = s[t - d];
        __syncthreads();
        if (t >= d) s[t] += v;
        __syncthreads();
    }
    int excl = s[t] - cnt;
    if (t == 255) base = atomicAdd(&g_base[0], s[255]);
    __syncthreads();
    if (g < G) {
        int o = base + excl;
        g_ofs[g] = o;
        g_cur[g] = o;
    }
}

// ---------------------------------------------------------------------------
// 3) build permutation — int4 vectorized, 4 independent fetch-adds/thread
// ---------------------------------------------------------------------------
__global__ void __launch_bounds__(256) perm_kernel(
    const int* __restrict__ gid, int n4, int n)
{
    int i = blockIdx.x * blockDim.x + threadIdx.x;
    if (i < n4) {
        int4 g4 = reinterpret_cast<const int4*>(gid)[i];
        int p = i * 4;
        int p0 = atomicAdd(&g_cur[min(max(g4.x, 0), G - 1)], 1);
        int p1 = atomicAdd(&g_cur[min(max(g4.y, 0), G - 1)], 1);
        int p2 = atomicAdd(&g_cur[min(max(g4.z, 0), G - 1)], 1);
        int p3 = atomicAdd(&g_cur[min(max(g4.w, 0), G - 1)], 1);
        g_perm[p0] = p;
        g_perm[p1] = p + 1;
        g_perm[p2] = p + 2;
        g_perm[p3] = p + 3;
    }
    int t = n4 * 4 + i;
    if (i < (n - n4 * 4)) {
        int g = gid[t];
        int pos = atomicAdd(&g_cur[min(max(g, 0), G - 1)], 1);
        g_perm[pos] = t;
    }
}

// ---------------------------------------------------------------------------
// 4) group-major reduce + broadcast write. One warp per group: 32 lanes hold
//    all 128 channels as float4 in registers. Zero float atomics.
// ---------------------------------------------------------------------------
__global__ void __launch_bounds__(256) reduce_write_kernel(
    const float* __restrict__ feat,
    float* __restrict__ out)
{
    int warp = (blockIdx.x * blockDim.x + threadIdx.x) >> 5;
    int lane = threadIdx.x & 31;
    if (warp >= G) return;

    int start = g_ofs[warp];
    int cnt   = g_hist[warp];
    if (cnt == 0) return;

    float4 acc = make_float4(0.f, 0.f, 0.f, 0.f);

    // software-pipelined: prefetch next perm entry while loading current row
    int p = g_perm[start];
    for (int i = 0; i < cnt; i++) {
        int pn = (i + 1 < cnt) ? g_perm[start + i + 1] : 0;
        const float4* frow = reinterpret_cast<const float4*>(feat + (size_t)p * C);
        float4 v = frow[lane];
        acc.x += v.x; acc.y += v.y; acc.z += v.z; acc.w += v.w;
        p = pn;
    }

    float inv = 1.0f / (float)cnt;
    acc.x *= inv; acc.y *= inv; acc.z *= inv; acc.w *= inv;

    for (int i = 0; i < cnt; i++) {
        int q = g_perm[start + i];  // L1 hit (read moments ago)
        float4* orow = reinterpret_cast<float4*>(out + (size_t)q * C);
        orow[lane] = acc;
    }
}

// ---------------------------------------------------------------------------
// Launch. Inputs: [0] ref_bxyz (unused), [1] ref_feat f32 [N,128],
// [2] group_ids int32 [N]. Output: [N,128] f32.
// ---------------------------------------------------------------------------
extern "C" void kernel_launch(void* const* d_in, const int* in_sizes, int n_in,
                              void* d_out, int out_size) {
    const float* feat = (const float*)d_in[1];
    const int* gid = (const int*)d_in[2];
    float* out = (float*)d_out;

    const int n = in_sizes[2];  // 1M points
    const int n4 = n / 4;

    init_kernel<<<592, 256>>>();

    int vblocks = (n4 + 255) / 256;
    hist_kernel<<<vblocks, 256>>>(gid, n4, n);

    offsets_kernel<<<(G + 255) / 256, 256>>>();

    perm_kernel<<<vblocks, 256>>>(gid, n4, n);

    // one warp per group, 8 warps per block
    reduce_write_kernel<<<(G + 7) / 8, 256>>>(feat, out);
}

// round 13
// speedup vs baseline: 1.0113x; 1.0113x over previous
#include <cuda_runtime.h>
#include <cstdint>

#define C 128
#define G 100000
#define NPTS_MAX 1000000

// Scratch (device globals — no allocation).
__device__ int g_hist[G];        // per-group counts (built by rank pass)
__device__ int g_base[1];        // global offset counter
__device__ int g_ofs[G];         // per-group start offset into perm
__device__ int g_rank[NPTS_MAX]; // per-point rank within its group
__device__ int g_perm[NPTS_MAX]; // point indices, grouped contiguously

__device__ __forceinline__ int clampg(int g) { return min(max(g, 0), G - 1); }

// ---------------------------------------------------------------------------
// 0) zero histogram + global counter
// ---------------------------------------------------------------------------
__global__ void init_kernel() {
    int idx = blockIdx.x * blockDim.x + threadIdx.x;
    int stride = gridDim.x * blockDim.x;
    for (int i = idx; i < G; i += stride) g_hist[i] = 0;
    if (idx == 0) g_base[0] = 0;
}

// ---------------------------------------------------------------------------
// 1) rank pass: ONE returning atomic per point builds counts AND ranks.
//    (replaces separate hist + perm-cursor atomic passes)
// ---------------------------------------------------------------------------
__global__ void __launch_bounds__(256) rank_kernel(
    const int* __restrict__ gid, int n4, int n)
{
    int i = blockIdx.x * blockDim.x + threadIdx.x;
    if (i < n4) {
        int4 g4 = reinterpret_cast<const int4*>(gid)[i];
        int r0 = atomicAdd(&g_hist[clampg(g4.x)], 1);
        int r1 = atomicAdd(&g_hist[clampg(g4.y)], 1);
        int r2 = atomicAdd(&g_hist[clampg(g4.z)], 1);
        int r3 = atomicAdd(&g_hist[clampg(g4.w)], 1);
        reinterpret_cast<int4*>(g_rank)[i] = make_int4(r0, r1, r2, r3);
    }
    int t = n4 * 4 + i;
    if (i < (n - n4 * 4)) {
        g_rank[t] = atomicAdd(&g_hist[clampg(gid[t])], 1);
    }
}

// ---------------------------------------------------------------------------
// 2) offsets: block-local exclusive scan + one atomicAdd per block
// ---------------------------------------------------------------------------
__global__ void __launch_bounds__(256) offsets_kernel()
{
    __shared__ int s[256];
    __shared__ int base;
    int t = threadIdx.x;
    int g = blockIdx.x * 256 + t;
    int cnt = (g < G) ? g_hist[g] : 0;
    s[t] = cnt;
    __syncthreads();
    for (int d = 1; d < 256; d <<= 1) {
        int v = 0;
        if (t >= d) v = s[t - d];
        __syncthreads();
        if (t >= d) s[t] += v;
        __syncthreads();
    }
    int excl = s[t] - cnt;
    if (t == 255) base = atomicAdd(&g_base[0], s[255]);
    __syncthreads();
    if (g < G) g_ofs[g] = base + excl;
}

// ---------------------------------------------------------------------------
// 3) place pass: perm[ofs[g] + rank[p]] = p.  ZERO atomics — pure mem ops.
// ---------------------------------------------------------------------------
__global__ void __launch_bounds__(256) place_kernel(
    const int* __restrict__ gid, int n4, int n)
{
    int i = blockIdx.x * blockDim.x + threadIdx.x;
    if (i < n4) {
        int4 g4 = reinterpret_cast<const int4*>(gid)[i];
        int4 r4 = reinterpret_cast<const int4*>(g_rank)[i];
        int p = i * 4;
        g_perm[g_ofs[clampg(g4.x)] + r4.x] = p;
        g_perm[g_ofs[clampg(g4.y)] + r4.y] = p + 1;
        g_perm[g_ofs[clampg(g4.z)] + r4.z] = p + 2;
        g_perm[g_ofs[clampg(g4.w)] + r4.w] = p + 3;
    }
    int t = n4 * 4 + i;
    if (i < (n - n4 * 4)) {
        g_perm[g_ofs[clampg(gid[t])] + g_rank[t]] = t;
    }
}

// ---------------------------------------------------------------------------
// 4) group-major reduce + broadcast write. One warp per group; 32 lanes hold
//    all 128 channels as float4 in registers. Member indices fetched with ONE
//    coalesced 32-lane load per 32-chunk, broadcast via shfl (no serial LDGs).
// ---------------------------------------------------------------------------
__global__ void __launch_bounds__(256) reduce_write_kernel(
    const float* __restrict__ feat,
    float* __restrict__ out)
{
    int warp = (blockIdx.x * blockDim.x + threadIdx.x) >> 5;
    int lane = threadIdx.x & 31;
    if (warp >= G) return;

    int start = g_ofs[warp];
    int cnt   = g_hist[warp];
    if (cnt == 0) return;

    float4 acc = make_float4(0.f, 0.f, 0.f, 0.f);

    for (int base = 0; base < cnt; base += 32) {
        int m = min(32, cnt - base);
        int idx = 0;
        if (lane < m) idx = g_perm[start + base + lane];
        #pragma unroll 4
        for (int j = 0; j < m; j++) {
            int p = __shfl_sync(0xffffffffu, idx, j);
            float4 v = reinterpret_cast<const float4*>(feat + (size_t)p * C)[lane];
            acc.x += v.x; acc.y += v.y; acc.z += v.z; acc.w += v.w;
        }
    }

    float inv = 1.0f / (float)cnt;
    acc.x *= inv; acc.y *= inv; acc.z *= inv; acc.w *= inv;

    for (int base = 0; base < cnt; base += 32) {
        int m = min(32, cnt - base);
        int idx = 0;
        if (lane < m) idx = g_perm[start + base + lane];   // L1 hit
        #pragma unroll 4
        for (int j = 0; j < m; j++) {
            int q = __shfl_sync(0xffffffffu, idx, j);
            reinterpret_cast<float4*>(out + (size_t)q * C)[lane] = acc;
        }
    }
}

// ---------------------------------------------------------------------------
// Launch. Inputs: [0] ref_bxyz (unused), [1] ref_feat f32 [N,128],
// [2] group_ids int32 [N]. Output: [N,128] f32.
// ---------------------------------------------------------------------------
extern "C" void kernel_launch(void* const* d_in, const int* in_sizes, int n_in,
                              void* d_out, int out_size) {
    const float* feat = (const float*)d_in[1];
    const int* gid = (const int*)d_in[2];
    float* out = (float*)d_out;

    const int n = in_sizes[2];  // 1M points
    const int n4 = n / 4;

    init_kernel<<<592, 256>>>();

    int vblocks = (n4 + 255) / 256;
    rank_kernel<<<vblocks, 256>>>(gid, n4, n);

    offsets_kernel<<<(G + 255) / 256, 256>>>();

    place_kernel<<<vblocks, 256>>>(gid, n4, n);

    // one warp per group, 8 warps per block
    reduce_write_kernel<<<(G + 7) / 8, 256>>>(feat, out);
}

// round 14
// speedup vs baseline: 1.0257x; 1.0143x over previous
#include <cuda_runtime.h>
#include <cstdint>

#define C 128
#define G 100000
#define NPTS_MAX 1000000

// Scratch (device globals — zero-initialized at module load; every run
// re-zeroes what it dirtied, so each graph replay starts from zeros).
__device__ int g_hist[G];        // per-group counts (built by rank pass)
__device__ int g_base[1];        // global offset counter
__device__ int g_ofs[G];         // per-group start offset into perm
__device__ int g_rank[NPTS_MAX]; // per-point rank within its group
__device__ int g_perm[NPTS_MAX]; // point indices, grouped contiguously

__device__ __forceinline__ int clampg(int g) { return min(max(g, 0), G - 1); }

// ---------------------------------------------------------------------------
// 1) rank pass: ONE returning atomic per point builds counts AND ranks.
//    (g_hist starts at zero: initial static init, then self-clean in reduce)
// ---------------------------------------------------------------------------
__global__ void __launch_bounds__(256) rank_kernel(
    const int* __restrict__ gid, int n4, int n)
{
    int i = blockIdx.x * blockDim.x + threadIdx.x;
    if (i < n4) {
        int4 g4 = reinterpret_cast<const int4*>(gid)[i];
        int r0 = atomicAdd(&g_hist[clampg(g4.x)], 1);
        int r1 = atomicAdd(&g_hist[clampg(g4.y)], 1);
        int r2 = atomicAdd(&g_hist[clampg(g4.z)], 1);
        int r3 = atomicAdd(&g_hist[clampg(g4.w)], 1);
        reinterpret_cast<int4*>(g_rank)[i] = make_int4(r0, r1, r2, r3);
    }
    int t = n4 * 4 + i;
    if (i < (n - n4 * 4)) {
        g_rank[t] = atomicAdd(&g_hist[clampg(gid[t])], 1);
    }
}

// ---------------------------------------------------------------------------
// 2) offsets: warp shfl-scan + 1-warp combine + one atomicAdd per block.
//    Group ordering across blocks is nondeterministic; irrelevant.
// ---------------------------------------------------------------------------
__global__ void __launch_bounds__(256) offsets_kernel()
{
    __shared__ int wsum[8];
    __shared__ int base;
    int t = threadIdx.x;
    int lane = t & 31;
    int w = t >> 5;
    int g = blockIdx.x * 256 + t;
    int cnt = (g < G) ? g_hist[g] : 0;

    // inclusive warp scan
    int v = cnt;
    #pragma unroll
    for (int d = 1; d < 32; d <<= 1) {
        int o = __shfl_up_sync(0xffffffffu, v, d);
        if (lane >= d) v += o;
    }
    if (lane == 31) wsum[w] = v;
    __syncthreads();

    if (w == 0) {
        int s = (lane < 8) ? wsum[lane] : 0;
        #pragma unroll
        for (int d = 1; d < 8; d <<= 1) {
            int o = __shfl_up_sync(0xffffffffu, s, d);
            if (lane >= d) s += o;
        }
        if (lane < 8) wsum[lane] = s;       // inclusive warp totals
        if (lane == 7) base = atomicAdd(&g_base[0], s);  // block total
    }
    __syncthreads();

    int warp_excl = (w == 0) ? 0 : wsum[w - 1];
    int excl = warp_excl + (v - cnt);
    if (g < G) g_ofs[g] = base + excl;
}

// ---------------------------------------------------------------------------
// 3) place pass: perm[ofs[g] + rank[p]] = p.  ZERO atomics.
// ---------------------------------------------------------------------------
__global__ void __launch_bounds__(256) place_kernel(
    const int* __restrict__ gid, int n4, int n)
{
    int i = blockIdx.x * blockDim.x + threadIdx.x;
    if (i < n4) {
        int4 g4 = reinterpret_cast<const int4*>(gid)[i];
        int4 r4 = reinterpret_cast<const int4*>(g_rank)[i];
        int p = i * 4;
        g_perm[g_ofs[clampg(g4.x)] + r4.x] = p;
        g_perm[g_ofs[clampg(g4.y)] + r4.y] = p + 1;
        g_perm[g_ofs[clampg(g4.z)] + r4.z] = p + 2;
        g_perm[g_ofs[clampg(g4.w)] + r4.w] = p + 3;
    }
    int t = n4 * 4 + i;
    if (i < (n - n4 * 4)) {
        g_perm[g_ofs[clampg(gid[t])] + g_rank[t]] = t;
    }
}

// ---------------------------------------------------------------------------
// 4) group-major reduce + broadcast write. One warp per group; 32 lanes hold
//    all 128 channels as float4 in registers. Coalesced perm loads + shfl.
//    SELF-CLEAN: each warp zeroes its own g_hist entry after consuming it;
//    thread (0,0) zeroes g_base. Next graph replay starts from zeros.
// ---------------------------------------------------------------------------
__global__ void __launch_bounds__(256) reduce_write_kernel(
    const float* __restrict__ feat,
    float* __restrict__ out)
{
    int warp = (blockIdx.x * blockDim.x + threadIdx.x) >> 5;
    int lane = threadIdx.x & 31;

    if (blockIdx.x == 0 && threadIdx.x == 0) g_base[0] = 0;
    if (warp >= G) return;

    int start = g_ofs[warp];
    int cnt   = g_hist[warp];
    if (lane == 0 && cnt != 0) g_hist[warp] = 0;   // self-clean for next run
    if (cnt == 0) return;

    float4 acc = make_float4(0.f, 0.f, 0.f, 0.f);

    for (int base = 0; base < cnt; base += 32) {
        int m = min(32, cnt - base);
        int idx = 0;
        if (lane < m) idx = g_perm[start + base + lane];
        #pragma unroll 4
        for (int j = 0; j < m; j++) {
            int p = __shfl_sync(0xffffffffu, idx, j);
            float4 v = reinterpret_cast<const float4*>(feat + (size_t)p * C)[lane];
            acc.x += v.x; acc.y += v.y; acc.z += v.z; acc.w += v.w;
        }
    }

    float inv = 1.0f / (float)cnt;
    acc.x *= inv; acc.y *= inv; acc.z *= inv; acc.w *= inv;

    for (int base = 0; base < cnt; base += 32) {
        int m = min(32, cnt - base);
        int idx = 0;
        if (lane < m) idx = g_perm[start + base + lane];   // L1 hit
        #pragma unroll 4
        for (int j = 0; j < m; j++) {
            int q = __shfl_sync(0xffffffffu, idx, j);
            reinterpret_cast<float4*>(out + (size_t)q * C)[lane] = acc;
        }
    }
}

// ---------------------------------------------------------------------------
// Launch. Inputs: [0] ref_bxyz (unused), [1] ref_feat f32 [N,128],
// [2] group_ids int32 [N]. Output: [N,128] f32.
// ---------------------------------------------------------------------------
extern "C" void kernel_launch(void* const* d_in, const int* in_sizes, int n_in,
                              void* d_out, int out_size) {
    const float* feat = (const float*)d_in[1];
    const int* gid = (const int*)d_in[2];
    float* out = (float*)d_out;

    const int n = in_sizes[2];  // 1M points
    const int n4 = n / 4;

    int vblocks = (n4 + 255) / 256;
    rank_kernel<<<vblocks, 256>>>(gid, n4, n);

    offsets_kernel<<<(G + 255) / 256, 256>>>();

    place_kernel<<<vblocks, 256>>>(gid, n4, n);

    // one warp per group, 8 warps per block
    reduce_write_kernel<<<(G + 7) / 8, 256>>>(feat, out);
}

// round 15
// speedup vs baseline: 1.0304x; 1.0046x over previous
#include <cuda_runtime.h>
#include <cstdint>

#define C 128
#define G 100000
#define NPTS_MAX 1000000

// Scratch (device globals — zero-init at load; self-cleaning per run).
// g_head[g]: encoded head of group g's member list (0 = empty, else p+1).
// g_next[p]: encoded next member after p (0 = end). Fully rewritten each run.
__device__ int g_head[G];
__device__ int g_next[NPTS_MAX];

__device__ __forceinline__ int clampg(int g) { return min(max(g, 0), G - 1); }

// ---------------------------------------------------------------------------
// 1) build per-group linked lists: one returning atomic per point.
//    next[p] = old head; head[g] = p+1. List order is arbitrary (irrelevant).
// ---------------------------------------------------------------------------
__global__ void __launch_bounds__(256) build_kernel(
    const int* __restrict__ gid, int n4, int n)
{
    int i = blockIdx.x * blockDim.x + threadIdx.x;
    if (i < n4) {
        int4 g4 = reinterpret_cast<const int4*>(gid)[i];
        int p = i * 4;
        int o0 = atomicExch(&g_head[clampg(g4.x)], p + 1);
        int o1 = atomicExch(&g_head[clampg(g4.y)], p + 2);
        int o2 = atomicExch(&g_head[clampg(g4.z)], p + 3);
        int o3 = atomicExch(&g_head[clampg(g4.w)], p + 4);
        reinterpret_cast<int4*>(g_next)[i] = make_int4(o0, o1, o2, o3);
    }
    int t = n4 * 4 + i;
    if (i < (n - n4 * 4)) {
        g_next[t] = atomicExch(&g_head[clampg(gid[t])], t + 1);
    }
}

// ---------------------------------------------------------------------------
// 2) reduce + broadcast write. One warp per group; 32 lanes hold all 128
//    channels as float4 in registers. Lane 0 chases the list and broadcasts
//    each member via shfl; member ids are banked in registers (lane j keeps
//    member j) so the write pass needs no re-walk for cnt <= 32.
//    SELF-CLEAN: head[warp] reset to 0 after being read.
// ---------------------------------------------------------------------------
__global__ void __launch_bounds__(256) reduce_write_kernel(
    const float* __restrict__ feat,
    float* __restrict__ out)
{
    int warp = (blockIdx.x * blockDim.x + threadIdx.x) >> 5;
    int lane = threadIdx.x & 31;
    if (warp >= G) return;

    int head = g_head[warp];                 // all lanes: broadcast load
    if (head == 0) return;                   // empty group (stays clean)
    if (lane == 0) g_head[warp] = 0;         // self-clean for next replay

    float4 acc = make_float4(0.f, 0.f, 0.f, 0.f);
    int cnt = 0;
    int save = 0;                            // lane j banks member j (enc +1)

    int p = head;                            // encoded (+1)
    while (p != 0) {
        int q = p - 1;
        float4 v = reinterpret_cast<const float4*>(feat + (size_t)q * C)[lane];
        acc.x += v.x; acc.y += v.y; acc.z += v.z; acc.w += v.w;
        if (lane == (cnt & 31)) save = p;
        cnt++;
        int np = 0;
        if (lane == 0) np = g_next[q];
        p = __shfl_sync(0xffffffffu, np, 0);
    }

    float inv = 1.0f / (float)cnt;
    acc.x *= inv; acc.y *= inv; acc.z *= inv; acc.w *= inv;

    if (cnt <= 32) {
        // member ids live in registers — no memory re-walk
        for (int j = 0; j < cnt; j++) {
            int q = __shfl_sync(0xffffffffu, save, j) - 1;
            reinterpret_cast<float4*>(out + (size_t)q * C)[lane] = acc;
        }
    } else {
        // rare tail (Poisson(10): P(cnt>32) ~ 1e-8): re-chase (next is L1-hot)
        p = head;
        while (p != 0) {
            int q = p - 1;
            reinterpret_cast<float4*>(out + (size_t)q * C)[lane] = acc;
            int np = 0;
            if (lane == 0) np = g_next[q];
            p = __shfl_sync(0xffffffffu, np, 0);
        }
    }
}

// ---------------------------------------------------------------------------
// Launch. Inputs: [0] ref_bxyz (unused), [1] ref_feat f32 [N,128],
// [2] group_ids int32 [N]. Output: [N,128] f32.
// ---------------------------------------------------------------------------
extern "C" void kernel_launch(void* const* d_in, const int* in_sizes, int n_in,
                              void* d_out, int out_size) {
    const float* feat = (const float*)d_in[1];
    const int* gid = (const int*)d_in[2];
    float* out = (float*)d_out;

    const int n = in_sizes[2];  // 1M points
    const int n4 = n / 4;

    build_kernel<<<(n4 + 255) / 256, 256>>>(gid, n4, n);

    // one warp per group, 8 warps per block
    reduce_write_kernel<<<(G + 7) / 8, 256>>>(feat, out);
}

// round 16
// speedup vs baseline: 1.0676x; 1.0361x over previous
#include <cuda_runtime.h>
#include <cstdint>

#define C 128
#define G 100000
#define NPTS_MAX 1000000
#define SLOTS 32   // per-group direct slots; beyond -> overflow list (P ~ 5e-10)

// Scratch (device globals — zero-init at load; self-cleaning per run).
__device__ int g_hist[G];            // per-group counts (self-cleaned)
__device__ int g_slot[G * SLOTS];    // member ids, slot = g*32 + rank (no clean needed)
__device__ int g_ovf[G];             // overflow list head, 0 = empty (self-cleaned)
__device__ int g_next[NPTS_MAX];     // overflow chain (encoded +1; only overflow entries used)

__device__ __forceinline__ int clampg(int g) { return min(max(g, 0), G - 1); }

__device__ __forceinline__ void build_one(int g, int p) {
    int r = atomicAdd(&g_hist[g], 1);
    if (r < SLOTS) {
        g_slot[g * SLOTS + r] = p;
    } else {
        g_next[p] = atomicExch(&g_ovf[g], p + 1);   // rare spill
    }
}

// ---------------------------------------------------------------------------
// 1) ONE-PASS build: rank via returning atomic + direct slot store.
//    (atomic latency and scattered stores overlap in the same kernel)
// ---------------------------------------------------------------------------
__global__ void __launch_bounds__(256) build_kernel(
    const int* __restrict__ gid, int n4, int n)
{
    int i = blockIdx.x * blockDim.x + threadIdx.x;
    if (i < n4) {
        int4 g4 = reinterpret_cast<const int4*>(gid)[i];
        int p = i * 4;
        build_one(clampg(g4.x), p);
        build_one(clampg(g4.y), p + 1);
        build_one(clampg(g4.z), p + 2);
        build_one(clampg(g4.w), p + 3);
    }
    int t = n4 * 4 + i;
    if (i < (n - n4 * 4)) {
        build_one(clampg(gid[t]), t);
    }
}

// ---------------------------------------------------------------------------
// 2) reduce + broadcast write. One warp per group; 32 lanes hold all 128
//    channels as float4 in registers. Member ids: ONE aligned 128B coalesced
//    load (slot[warp*32 + lane]) + shfl broadcast — no pointer chase.
//    SELF-CLEAN: hist (and ovf head if used) zeroed after consumption.
// ---------------------------------------------------------------------------
__global__ void __launch_bounds__(256) reduce_write_kernel(
    const float* __restrict__ feat,
    float* __restrict__ out)
{
    int warp = (blockIdx.x * blockDim.x + threadIdx.x) >> 5;
    int lane = threadIdx.x & 31;
    if (warp >= G) return;

    int cnt = g_hist[warp];                  // broadcast load
    if (cnt == 0) return;                    // empty: already clean
    if (lane == 0) g_hist[warp] = 0;         // self-clean for next replay

    int m = min(cnt, SLOTS);
    int idx = 0;
    if (lane < m) idx = g_slot[warp * SLOTS + lane];   // one 128B line

    float4 acc = make_float4(0.f, 0.f, 0.f, 0.f);

    #pragma unroll 4
    for (int j = 0; j < m; j++) {
        int p = __shfl_sync(0xffffffffu, idx, j);
        float4 v = reinterpret_cast<const float4*>(feat + (size_t)p * C)[lane];
        acc.x += v.x; acc.y += v.y; acc.z += v.z; acc.w += v.w;
    }

    int ovf_head = 0;
    if (cnt > SLOTS) {                       // practically never
        ovf_head = g_ovf[warp];
        if (lane == 0) g_ovf[warp] = 0;      // self-clean
        int p = ovf_head;
        while (p != 0) {
            int q = p - 1;
            float4 v = reinterpret_cast<const float4*>(feat + (size_t)q * C)[lane];
            acc.x += v.x; acc.y += v.y; acc.z += v.z; acc.w += v.w;
            int np = 0;
            if (lane == 0) np = g_next[q];
            p = __shfl_sync(0xffffffffu, np, 0);
        }
    }

    float inv = 1.0f / (float)cnt;
    acc.x *= inv; acc.y *= inv; acc.z *= inv; acc.w *= inv;

    #pragma unroll 4
    for (int j = 0; j < m; j++) {
        int q = __shfl_sync(0xffffffffu, idx, j);
        reinterpret_cast<float4*>(out + (size_t)q * C)[lane] = acc;
    }

    if (cnt > SLOTS) {
        int p = ovf_head;
        while (p != 0) {
            int q = p - 1;
            reinterpret_cast<float4*>(out + (size_t)q * C)[lane] = acc;
            int np = 0;
            if (lane == 0) np = g_next[q];
            p = __shfl_sync(0xffffffffu, np, 0);
        }
    }
}

// ---------------------------------------------------------------------------
// Launch. Inputs: [0] ref_bxyz (unused), [1] ref_feat f32 [N,128],
// [2] group_ids int32 [N]. Output: [N,128] f32.
// ---------------------------------------------------------------------------
extern "C" void kernel_launch(void* const* d_in, const int* in_sizes, int n_in,
                              void* d_out, int out_size) {
    const float* feat = (const float*)d_in[1];
    const int* gid = (const int*)d_in[2];
    float* out = (float*)d_out;

    const int n = in_sizes[2];  // 1M points
    const int n4 = n / 4;

    build_kernel<<<(n4 + 255) / 256, 256>>>(gid, n4, n);

    // one warp per group, 8 warps per block
    reduce_write_kernel<<<(G + 7) / 8, 256>>>(feat, out);
}